// round 1
// baseline (speedup 1.0000x reference)
#include <cuda_runtime.h>
#include <math.h>

#define HH 512
#define WW 512
#define NS 5000
#define SS 10
#define KK 20
#define HC 102
#define WC 102
#define NCELL (HC*WC)

// Scratch (static device globals — no runtime allocation)
__device__ float2 g_pts[NS*SS];        // bezier polyline points
__device__ int    g_cidx[NCELL*KK];    // per coarse cell: sorted top-K stroke indices
__device__ float  g_cw[NCELL*KK];      // per coarse cell: widths of those strokes (rank-aligned)

// ---------------------------------------------------------------------------
// Kernel 1: Bezier points. pts[n][j] = C + (1-t)^2 (S-C) + t^2 (E-C),
// with S = curve_s+loc, C = curve_c+loc, E = curve_e+loc, t = j/9.
// ---------------------------------------------------------------------------
__global__ void bezier_kernel(const float* __restrict__ cs,
                              const float* __restrict__ ce,
                              const float* __restrict__ cc,
                              const float* __restrict__ loc)
{
    int n = blockIdx.x * blockDim.x + threadIdx.x;
    if (n >= NS) return;
    float lx = loc[2*n], ly = loc[2*n+1];
    float sx = cs[2*n] + lx, sy = cs[2*n+1] + ly;
    float cx = cc[2*n] + lx, cy = cc[2*n+1] + ly;
    float ex = ce[2*n] + lx, ey = ce[2*n+1] + ly;
    float dsx = sx - cx, dsy = sy - cy;
    float dex = ex - cx, dey = ey - cy;
    const float dt = 1.0f / 9.0f;
#pragma unroll
    for (int j = 0; j < SS; j++) {
        float t   = (float)j * dt;
        float omt = 1.0f - t;
        float o2  = omt * omt;
        float t2  = t * t;
        float px  = cx + o2 * dsx + t2 * dex;
        float py  = cy + o2 * dsy + t2 * dey;
        g_pts[n*SS + j] = make_float2(px, py);
    }
}

// ---------------------------------------------------------------------------
// Kernel 2: per coarse cell top-K (ascending distance, stable ties).
// 128 threads/block = 64 cells x 2 parity chunks. Locations staged in SMEM
// tiles; per-thread sorted insertion list; 2-way merge at the end.
// ---------------------------------------------------------------------------
#define CPB 64     // cells per block
#define TILE 1000  // strokes per smem tile

__global__ void topk_kernel(const float* __restrict__ loc,
                            const float* __restrict__ width)
{
    __shared__ float2 s_loc[TILE];
    __shared__ float  s_d[128][KK];
    __shared__ int    s_i[128][KK];

    int tid   = threadIdx.x;       // 0..127
    int cl    = tid & 63;          // cell slot in block
    int chunk = tid >> 6;          // 0 or 1 (stroke parity)
    int cell  = blockIdx.x * CPB + cl;

    int ci = cell / WC;
    int cj = cell - ci * WC;
    const float STEPC = 512.0f / 101.0f;   // linspace(0,512,102) step
    float px = (float)ci * STEPC;
    float py = (float)cj * STEPC;

    float bd[KK];
    int   bi[KK];
#pragma unroll
    for (int k = 0; k < KK; k++) { bd[k] = 3.4e38f; bi[k] = -1; }

    for (int t0 = 0; t0 < NS; t0 += TILE) {
        int cnt = min(TILE, NS - t0);
        __syncthreads();
        for (int i = tid; i < cnt; i += blockDim.x)
            s_loc[i] = make_float2(loc[2*(t0+i)], loc[2*(t0+i)+1]);
        __syncthreads();
        for (int i = chunk; i < cnt; i += 2) {
            float2 L = s_loc[i];
            float dx = px - L.x, dy = py - L.y;
            float d  = dx*dx + dy*dy;
            if (d < bd[KK-1]) {
                int s = t0 + i;
                int j = KK - 1;
                while (j > 0 && bd[j-1] > d) {   // strict => stable (lower idx first)
                    bd[j] = bd[j-1]; bi[j] = bi[j-1]; j--;
                }
                bd[j] = d; bi[j] = s;
            }
        }
    }

#pragma unroll
    for (int k = 0; k < KK; k++) { s_d[tid][k] = bd[k]; s_i[tid][k] = bi[k]; }
    __syncthreads();

    if (tid < CPB && cell < NCELL) {
        int ra = tid, rb = tid + 64;
        int pa = 0, pb = 0;
#pragma unroll
        for (int o = 0; o < KK; o++) {
            float da = s_d[ra][pa], db = s_d[rb][pb];
            int   ia = s_i[ra][pa], ib = s_i[rb][pb];
            bool takeA = (da < db) || (da == db && ia < ib);
            int n = takeA ? ia : ib;
            if (takeA) pa++; else pb++;
            g_cidx[cell*KK + o] = n;
            g_cw  [cell*KK + o] = width[n];
        }
    }
}

// ---------------------------------------------------------------------------
// Kernel 3: per-pixel render. Streaming softmax over K strokes.
// ---------------------------------------------------------------------------
__global__ void render_kernel(const float* __restrict__ color,
                              float* __restrict__ out)
{
    int w = blockIdx.x * blockDim.x + threadIdx.x;
    int h = blockIdx.y * blockDim.y + threadIdx.y;
    if (h >= HH || w >= WW) return;

    const float STEPF = 512.0f / 511.0f;   // linspace(0,512,512) step
    float px = (float)h * STEPF;
    float py = (float)w * STEPF;

    const float SC = 102.0f / 512.0f;      // exact in fp32
    int ihc = (int)floorf((float)h * SC); if (ihc > HC-1) ihc = HC-1;
    int iwc = (int)floorf((float)w * SC); if (iwc > WC-1) iwc = WC-1;
    int cell = ihc * WC + iwc;

    // bilinear coords for width resize (half-pixel convention, edge clamp)
    float uh = ((float)h + 0.5f) * SC - 0.5f;
    uh = fminf(fmaxf(uh, 0.0f), (float)(HC-1));
    int h0 = (int)uh; float fh = uh - (float)h0; int h1 = min(h0+1, HC-1);
    float uw = ((float)w + 0.5f) * SC - 0.5f;
    uw = fminf(fmaxf(uw, 0.0f), (float)(WC-1));
    int w0 = (int)uw; float fw = uw - (float)w0; int w1 = min(w0+1, WC-1);

    const float* W00 = &g_cw[(h0*WC + w0)*KK];
    const float* W01 = &g_cw[(h0*WC + w1)*KK];
    const float* W10 = &g_cw[(h1*WC + w0)*KK];
    const float* W11 = &g_cw[(h1*WC + w1)*KK];
    const int*   IDX = &g_cidx[cell*KK];

    float M = -3.4e38f, ssum = 0.0f;
    float c0 = 0.0f, c1 = 0.0f, c2 = 0.0f, bsacc = 0.0f;
    float Dmin = 3.4e38f;

    for (int k = 0; k < KK; k++) {
        int n = __ldg(&IDX[k]);
        const float2* P = &g_pts[n*SS];
        float2 a = __ldg(&P[0]);
        float md = 3.4e38f;
#pragma unroll
        for (int s = 1; s < SS; s++) {
            float2 b = __ldg(&P[s]);
            float bax = b.x - a.x, bay = b.y - a.y;
            float pax = px - a.x,  pay = py - a.y;
            float denom = bax*bax + bay*bay;
            float t = (bax*pax + bay*pay) / denom;
            t = fminf(fmaxf(t, 0.0f), 1.0f);
            float cx = a.x + t*bax, cy = a.y + t*bay;
            float dx = px - cx,     dy = py - cy;
            md = fminf(md, dx*dx + dy*dy);
            a = b;
        }
        Dmin = fminf(Dmin, md);
        float L = 100000.0f / (1e-8f + md);

        float wk = (1.0f - fh) * ((1.0f - fw) * __ldg(&W00[k]) + fw * __ldg(&W01[k]))
                 +         fh  * ((1.0f - fw) * __ldg(&W10[k]) + fw * __ldg(&W11[k]));

        float r0 = __ldg(&color[n*3 + 0]);
        float r1 = __ldg(&color[n*3 + 1]);
        float r2 = __ldg(&color[n*3 + 2]);

        float e;
        if (L > M) {
            float r = __expf(M - L);      // rescale old accumulators
            ssum *= r; c0 *= r; c1 *= r; c2 *= r; bsacc *= r;
            M = L; e = 1.0f;
        } else {
            e = __expf(L - M);
        }
        ssum  += e;
        c0    += e * r0;
        c1    += e * r1;
        c2    += e * r2;
        bsacc += e * wk;
    }

    float inv = 1.0f / ssum;
    float bs  = bsacc * inv;
    float x   = bs - Dmin;
    float mask = 1.0f / (1.0f + expf(-x));
    float omm  = 1.0f - mask;

    int base = (h*WW + w) * 3;
    out[base + 0] = c0 * inv * mask + omm * 0.5f;
    out[base + 1] = c1 * inv * mask + omm * 0.5f;
    out[base + 2] = c2 * inv * mask + omm * 0.5f;
}

// ---------------------------------------------------------------------------
// Launch. Inputs (metadata order): curve_s, curve_e, curve_c, color, location, width
// ---------------------------------------------------------------------------
extern "C" void kernel_launch(void* const* d_in, const int* in_sizes, int n_in,
                              void* d_out, int out_size)
{
    const float* curve_s  = (const float*)d_in[0];
    const float* curve_e  = (const float*)d_in[1];
    const float* curve_c  = (const float*)d_in[2];
    const float* color    = (const float*)d_in[3];
    const float* location = (const float*)d_in[4];
    const float* width    = (const float*)d_in[5];
    float* out = (float*)d_out;

    bezier_kernel<<<(NS + 127)/128, 128>>>(curve_s, curve_e, curve_c, location);
    topk_kernel<<<(NCELL + CPB - 1)/CPB, 128>>>(location, width);

    dim3 blk(16, 16);
    dim3 grd(WW/16, HH/16);
    render_kernel<<<grd, blk>>>(color, out);
}

// round 2
// speedup vs baseline: 5.4765x; 5.4765x over previous
#include <cuda_runtime.h>
#include <math.h>
#include <float.h>

#define HH 512
#define WW 512
#define NS 5000
#define SS 10
#define NSEG 9
#define KK 20
#define HC 102
#define WC 102
#define NCELL (HC*WC)

#define CPB 32                               // cells per topk block
#define CHUNKS 8                             // stroke-parity chunks per cell
#define TPB (CPB*CHUNKS)                     // 256 threads
#define TOPK_BLOCKS ((NCELL + CPB - 1)/CPB)  // 326
#define BEZ_BLOCKS ((NS + TPB - 1)/TPB)      // 20
#define TILE 1000                            // strokes per smem tile (mult of CHUNKS)

// Scratch (static device globals — no runtime allocation)
__device__ float4 g_seg[NS*NSEG];    // per segment: ax, ay, dx, dy
__device__ float  g_sinv[NS*NSEG];   // per segment: 1/(dx^2+dy^2)
__device__ int    g_cidx[NCELL*KK];  // per coarse cell: sorted top-K stroke indices
__device__ float  g_cw[NCELL*KK];    // per coarse cell: widths (rank-aligned)

// ---------------------------------------------------------------------------
// Fused prep kernel:
//   blocks [0, TOPK_BLOCKS)            : per-coarse-cell top-K
//   blocks [TOPK_BLOCKS, +BEZ_BLOCKS)  : bezier points -> segment SoA
// ---------------------------------------------------------------------------
__global__ __launch_bounds__(TPB) void prep_kernel(
    const float* __restrict__ cs,
    const float* __restrict__ ce,
    const float* __restrict__ cc,
    const float* __restrict__ loc,
    const float* __restrict__ width)
{
    if (blockIdx.x >= TOPK_BLOCKS) {
        // ---------------- bezier + segment precompute ----------------
        int n = (blockIdx.x - TOPK_BLOCKS) * TPB + threadIdx.x;
        if (n >= NS) return;
        float lx = loc[2*n], ly = loc[2*n+1];
        float sx = cs[2*n] + lx, sy = cs[2*n+1] + ly;
        float cx = cc[2*n] + lx, cy = cc[2*n+1] + ly;
        float ex = ce[2*n] + lx, ey = ce[2*n+1] + ly;
        float dsx = sx - cx, dsy = sy - cy;
        float dex = ex - cx, dey = ey - cy;
        const float dt = 1.0f / 9.0f;
        float pxp[SS], pyp[SS];
#pragma unroll
        for (int j = 0; j < SS; j++) {
            float t   = (float)j * dt;
            float omt = 1.0f - t;
            float o2  = omt * omt;
            float t2  = t * t;
            pxp[j] = cx + o2 * dsx + t2 * dex;
            pyp[j] = cy + o2 * dsy + t2 * dey;
        }
#pragma unroll
        for (int s = 0; s < NSEG; s++) {
            float ax = pxp[s],     ay = pyp[s];
            float dx = pxp[s+1]-ax, dy = pyp[s+1]-ay;
            float denom = dx*dx + dy*dy;
            g_seg[n*NSEG + s]  = make_float4(ax, ay, dx, dy);
            g_sinv[n*NSEG + s] = 1.0f / denom;
        }
        return;
    }

    // ---------------- top-K per coarse cell ----------------
    __shared__ float2 s_loc[TILE];
    __shared__ float  s_d[TPB][KK];
    __shared__ int    s_i[TPB][KK];

    int tid   = threadIdx.x;
    int cl    = tid & (CPB-1);     // cell slot in block
    int chunk = tid >> 5;          // 0..7 (warp-uniform)
    int cell  = blockIdx.x * CPB + cl;

    int ci = cell / WC;
    int cj = cell - ci * WC;
    const float STEPC = 512.0f / 101.0f;   // linspace(0,512,102) step
    float px = (float)ci * STEPC;
    float py = (float)cj * STEPC;

    float bd[KK];
    int   bi[KK];
#pragma unroll
    for (int k = 0; k < KK; k++) { bd[k] = FLT_MAX; bi[k] = -1; }

    for (int t0 = 0; t0 < NS; t0 += TILE) {
        int cnt = min(TILE, NS - t0);
        __syncthreads();
        for (int i = tid; i < cnt; i += TPB)
            s_loc[i] = make_float2(loc[2*(t0+i)], loc[2*(t0+i)+1]);
        __syncthreads();
        for (int i = chunk; i < cnt; i += CHUNKS) {
            float2 L = s_loc[i];               // broadcast within warp
            float dx = px - L.x, dy = py - L.y;
            float d  = dx*dx + dy*dy;
            if (d < bd[KK-1]) {
                // register-resident bubble insert (stable: strict <, strokes
                // processed in increasing index within a thread)
                float pd = d; int pi = t0 + i;
#pragma unroll
                for (int k = 0; k < KK; k++) {
                    bool c = pd < bd[k];
                    float od = bd[k]; int oi = bi[k];
                    bd[k] = c ? pd : od;  bi[k] = c ? pi : oi;
                    pd    = c ? od : pd;  pi    = c ? oi : pi;
                }
            }
        }
    }

#pragma unroll
    for (int k = 0; k < KK; k++) { s_d[tid][k] = bd[k]; s_i[tid][k] = bi[k]; }
    __syncthreads();

    // 8-way merge of sorted lists, one thread per cell
    if (tid < CPB && cell < NCELL) {
        int p[CHUNKS];
#pragma unroll
        for (int c = 0; c < CHUNKS; c++) p[c] = 0;
#pragma unroll 1
        for (int o = 0; o < KK; o++) {
            float best = FLT_MAX; int bidx = 0x7fffffff; int bc = 0;
#pragma unroll
            for (int c = 0; c < CHUNKS; c++) {
                int row = cl + CPB * c;
                float dd = s_d[row][p[c]];
                int   ii = s_i[row][p[c]];
                if (dd < best || (dd == best && ii < bidx)) {
                    best = dd; bidx = ii; bc = c;
                }
            }
            p[bc]++;
            g_cidx[cell*KK + o] = bidx;
            g_cw  [cell*KK + o] = width[bidx];
        }
    }
}

// ---------------------------------------------------------------------------
// Render: 1 thread/pixel, warp = 8(w) x 4(h) patch (~2 coarse cells/warp).
// Branch-free streaming softmax; segment reciprocals precomputed.
// ---------------------------------------------------------------------------
__global__ __launch_bounds__(256) void render_kernel(
    const float* __restrict__ color,
    float* __restrict__ out)
{
    int w = blockIdx.x * 8  + threadIdx.x;
    int h = blockIdx.y * 32 + threadIdx.y;

    const float STEPF = 512.0f / 511.0f;   // linspace(0,512,512) step
    float px = (float)h * STEPF;
    float py = (float)w * STEPF;

    const float SC = 102.0f / 512.0f;      // exact in fp32
    int ihc = (int)floorf((float)h * SC); if (ihc > HC-1) ihc = HC-1;
    int iwc = (int)floorf((float)w * SC); if (iwc > WC-1) iwc = WC-1;
    int cell = ihc * WC + iwc;

    // bilinear coords for width resize (half-pixel convention, edge clamp)
    float uh = ((float)h + 0.5f) * SC - 0.5f;
    uh = fminf(fmaxf(uh, 0.0f), (float)(HC-1));
    int h0 = (int)uh; float fh = uh - (float)h0; int h1 = min(h0+1, HC-1);
    float uw = ((float)w + 0.5f) * SC - 0.5f;
    uw = fminf(fmaxf(uw, 0.0f), (float)(WC-1));
    int w0 = (int)uw; float fw = uw - (float)w0; int w1 = min(w0+1, WC-1);

    float c00 = (1.0f - fh) * (1.0f - fw);
    float c01 = (1.0f - fh) * fw;
    float c10 = fh * (1.0f - fw);
    float c11 = fh * fw;

    const float* W00 = &g_cw[(h0*WC + w0)*KK];
    const float* W01 = &g_cw[(h0*WC + w1)*KK];
    const float* W10 = &g_cw[(h1*WC + w0)*KK];
    const float* W11 = &g_cw[(h1*WC + w1)*KK];
    const int*   IDX = &g_cidx[cell*KK];

    float M = -FLT_MAX, ssum = 0.0f;
    float a0 = 0.0f, a1 = 0.0f, a2 = 0.0f, bsacc = 0.0f;
    float Dmin = FLT_MAX;

    for (int k = 0; k < KK; k++) {
        int n = __ldg(&IDX[k]);
        const float4* S4 = &g_seg[n*NSEG];
        const float*  SI = &g_sinv[n*NSEG];
        float md = FLT_MAX;
#pragma unroll
        for (int s = 0; s < NSEG; s++) {
            float4 sg = __ldg(&S4[s]);
            float inv = __ldg(&SI[s]);
            float pax = px - sg.x, pay = py - sg.y;
            float t = (sg.z*pax + sg.w*pay) * inv;
            t = fminf(fmaxf(t, 0.0f), 1.0f);
            float cx = sg.x + t*sg.z;
            float cy = sg.y + t*sg.w;
            float dx = px - cx, dy = py - cy;
            md = fminf(md, dx*dx + dy*dy);
        }
        Dmin = fminf(Dmin, md);
        float L = 100000.0f / (1e-8f + md);   // exact div: softmax-sensitive

        float wk = c00 * __ldg(&W00[k]) + c01 * __ldg(&W01[k])
                 + c10 * __ldg(&W10[k]) + c11 * __ldg(&W11[k]);

        float r0 = __ldg(&color[n*3 + 0]);
        float r1 = __ldg(&color[n*3 + 1]);
        float r2 = __ldg(&color[n*3 + 2]);

        float nM = fmaxf(M, L);
        float rr = __expf(M - nM);            // 1.0 when M unchanged
        float e  = __expf(L - nM);
        ssum  = ssum  * rr + e;
        a0    = a0    * rr + e * r0;
        a1    = a1    * rr + e * r1;
        a2    = a2    * rr + e * r2;
        bsacc = bsacc * rr + e * wk;
        M = nM;
    }

    float inv = 1.0f / ssum;
    float bs  = bsacc * inv;
    float x   = bs - Dmin;
    float mask = 1.0f / (1.0f + expf(-x));
    float omm  = 1.0f - mask;

    int base = (h*WW + w) * 3;
    out[base + 0] = a0 * inv * mask + omm * 0.5f;
    out[base + 1] = a1 * inv * mask + omm * 0.5f;
    out[base + 2] = a2 * inv * mask + omm * 0.5f;
}

// ---------------------------------------------------------------------------
// Launch. Inputs (metadata order): curve_s, curve_e, curve_c, color, location, width
// ---------------------------------------------------------------------------
extern "C" void kernel_launch(void* const* d_in, const int* in_sizes, int n_in,
                              void* d_out, int out_size)
{
    const float* curve_s  = (const float*)d_in[0];
    const float* curve_e  = (const float*)d_in[1];
    const float* curve_c  = (const float*)d_in[2];
    const float* color    = (const float*)d_in[3];
    const float* location = (const float*)d_in[4];
    const float* width    = (const float*)d_in[5];
    float* out = (float*)d_out;

    prep_kernel<<<TOPK_BLOCKS + BEZ_BLOCKS, TPB>>>(curve_s, curve_e, curve_c,
                                                   location, width);

    dim3 blk(8, 32);
    dim3 grd(WW/8, HH/32);
    render_kernel<<<grd, blk>>>(color, out);
}

// round 4
// speedup vs baseline: 6.7614x; 1.2346x over previous
#include <cuda_runtime.h>
#include <math.h>
#include <float.h>

#define HH 512
#define WW 512
#define NS 5000
#define SS 10
#define NSEG 9
#define KK 20
#define HC 102
#define WC 102
#define NCELL (HC*WC)

#define GB 32              // bins per axis
#define NBIN (GB*GB)       // 1024
#define BINW 16.0f         // bin width in px
#define INV_BINW 0.0625f

// Scratch (static device globals — no runtime allocation)
__device__ float4 g_seg[NS*NSEG];    // per segment: ax, ay, dx, dy
__device__ float  g_sinv[NS*NSEG];   // per segment: 1/(dx^2+dy^2)
__device__ float4 g_col4[NS];        // stroke color (padded)
__device__ int    g_binoff[NBIN+1];  // bin start offsets (exclusive scan)
__device__ float2 g_bloc[NS];        // stroke locations, grouped by bin
__device__ int    g_bidx[NS];        // stroke indices,  grouped by bin
__device__ int    g_cidx[NCELL*KK];  // per coarse cell: sorted top-K stroke indices
__device__ float  g_cw[NCELL*KK];    // per coarse cell: widths (rank-aligned)

// ---------------------------------------------------------------------------
// Kernel 1: block 0 builds the spatial bin structure (single block, smem
// count + scan + scatter). Blocks 1..5 do bezier -> segment precompute and
// pack colors.
// ---------------------------------------------------------------------------
__global__ __launch_bounds__(1024) void build_kernel(
    const float* __restrict__ cs,
    const float* __restrict__ ce,
    const float* __restrict__ cc,
    const float* __restrict__ loc,
    const float* __restrict__ color)
{
    int tid = threadIdx.x;

    if (blockIdx.x == 0) {
        __shared__ int s_cnt[NBIN];   // counts, then running offsets
        __shared__ int s_scan[NBIN];

        s_cnt[tid] = 0;
        __syncthreads();

        // count
        for (int i = tid; i < NS; i += 1024) {
            float x = loc[2*i], y = loc[2*i+1];
            int bx = min(GB-1, (int)(x * INV_BINW));
            int by = min(GB-1, (int)(y * INV_BINW));
            atomicAdd(&s_cnt[bx*GB + by], 1);
        }
        __syncthreads();

        // inclusive scan (Hillis-Steele)
        int own = s_cnt[tid];
        s_scan[tid] = own;
        __syncthreads();
        for (int off = 1; off < NBIN; off <<= 1) {
            int v = (tid >= off) ? s_scan[tid - off] : 0;
            __syncthreads();
            s_scan[tid] += v;
            __syncthreads();
        }
        int excl = s_scan[tid] - own;
        g_binoff[tid] = excl;
        if (tid == NBIN-1) g_binoff[NBIN] = s_scan[NBIN-1];
        s_cnt[tid] = excl;        // becomes the running cursor
        __syncthreads();

        // scatter
        for (int i = tid; i < NS; i += 1024) {
            float x = loc[2*i], y = loc[2*i+1];
            int bx = min(GB-1, (int)(x * INV_BINW));
            int by = min(GB-1, (int)(y * INV_BINW));
            int pos = atomicAdd(&s_cnt[bx*GB + by], 1);
            g_bloc[pos] = make_float2(x, y);
            g_bidx[pos] = i;
        }
        return;
    }

    // ---------------- bezier + segment precompute + color pack ----------------
    int n = (blockIdx.x - 1) * 1024 + tid;
    if (n >= NS) return;
    float lx = loc[2*n], ly = loc[2*n+1];
    float sx = cs[2*n] + lx, sy = cs[2*n+1] + ly;
    float cx = cc[2*n] + lx, cy = cc[2*n+1] + ly;
    float ex = ce[2*n] + lx, ey = ce[2*n+1] + ly;
    float dsx = sx - cx, dsy = sy - cy;
    float dex = ex - cx, dey = ey - cy;
    const float dt = 1.0f / 9.0f;
    float pxp[SS], pyp[SS];
#pragma unroll
    for (int j = 0; j < SS; j++) {
        float t   = (float)j * dt;
        float omt = 1.0f - t;
        float o2  = omt * omt;
        float t2  = t * t;
        pxp[j] = cx + o2 * dsx + t2 * dex;
        pyp[j] = cy + o2 * dsy + t2 * dey;
    }
#pragma unroll
    for (int s = 0; s < NSEG; s++) {
        float ax = pxp[s],      ay = pyp[s];
        float dx = pxp[s+1]-ax, dy = pyp[s+1]-ay;
        float denom = dx*dx + dy*dy;
        g_seg[n*NSEG + s]  = make_float4(ax, ay, dx, dy);
        g_sinv[n*NSEG + s] = 1.0f / denom;
    }
    g_col4[n] = make_float4(color[n*3], color[n*3+1], color[n*3+2], 0.0f);
}

// ---------------------------------------------------------------------------
// Kernel 2: per-coarse-cell exact top-K via spatial grid ring walk.
// One thread per cell; block = 16x16 cell tile (warp = 2x16, shared bins).
// Lexicographic (dist, idx) keys => exact JAX top_k semantics, independent
// of candidate arrival order.
// ---------------------------------------------------------------------------
__global__ __launch_bounds__(256) void topk_kernel(const float* __restrict__ width)
{
    int ti = threadIdx.x >> 4;     // 0..15
    int tj = threadIdx.x & 15;     // 0..15
    int ci = blockIdx.y * 16 + ti;
    int cj = blockIdx.x * 16 + tj;
    if (ci >= HC || cj >= WC) return;

    const float STEPC = 512.0f / 101.0f;
    float px = (float)ci * STEPC;
    float py = (float)cj * STEPC;

    float bd[KK];
    int   bi[KK];
#pragma unroll
    for (int k = 0; k < KK; k++) { bd[k] = FLT_MAX; bi[k] = 0x7fffffff; }

    int bx = min(GB-1, (int)(px * INV_BINW));
    int by = min(GB-1, (int)(py * INV_BINW));

    for (int r = 0; r < GB; r++) {
        int x0 = bx - r, x1 = bx + r;
        int y0 = by - r, y1 = by + r;
        int cx0 = max(x0, 0), cx1 = min(x1, GB-1);
        int cy0 = max(y0, 0), cy1 = min(y1, GB-1);

        // process bins with Chebyshev distance exactly r
        for (int xx = cx0; xx <= cx1; xx++) {
            for (int yy = cy0; yy <= cy1; yy++) {
                if (r > 0 && xx != x0 && xx != x1 && yy != y0 && yy != y1)
                    continue;   // interior already done
                int b  = xx*GB + yy;
                int s0 = g_binoff[b];
                int s1 = g_binoff[b+1];
                for (int j = s0; j < s1; j++) {
                    float2 L = g_bloc[j];
                    float dx = px - L.x, dy = py - L.y;
                    float d  = dx*dx + dy*dy;
                    int idx  = g_bidx[j];
                    if (d < bd[KK-1] || (d == bd[KK-1] && idx < bi[KK-1])) {
                        float pd = d; int pi = idx;
#pragma unroll
                        for (int k = 0; k < KK; k++) {
                            bool c = (pd < bd[k]) || (pd == bd[k] && pi < bi[k]);
                            float od = bd[k]; int oi = bi[k];
                            bd[k] = c ? pd : od;  bi[k] = c ? pi : oi;
                            pd    = c ? od : pd;  pi    = c ? oi : pi;
                        }
                    }
                }
            }
        }

        // exact termination: unprocessed strokes are outside the processed
        // square => dist >= m
        float m = fminf(fminf(px - (float)x0 * BINW, (float)(x1+1) * BINW - px),
                        fminf(py - (float)y0 * BINW, (float)(y1+1) * BINW - py));
        if (bd[KK-1] < m * m) break;
    }

    int cell = ci * WC + cj;
#pragma unroll
    for (int o = 0; o < KK; o++) {
        g_cidx[cell*KK + o] = bi[o];
        g_cw  [cell*KK + o] = width[bi[o]];
    }
}

// ---------------------------------------------------------------------------
// Kernel 3: per-pixel render. Branch-free streaming softmax.
// ---------------------------------------------------------------------------
__global__ __launch_bounds__(256, 5) void render_kernel(float* __restrict__ out)
{
    int w = blockIdx.x * 8  + threadIdx.x;
    int h = blockIdx.y * 32 + threadIdx.y;

    const float STEPF = 512.0f / 511.0f;
    float px = (float)h * STEPF;
    float py = (float)w * STEPF;

    const float SC = 102.0f / 512.0f;      // exact in fp32
    int ihc = (int)floorf((float)h * SC); if (ihc > HC-1) ihc = HC-1;
    int iwc = (int)floorf((float)w * SC); if (iwc > WC-1) iwc = WC-1;
    int cell = ihc * WC + iwc;

    // bilinear coords for width resize (half-pixel convention, edge clamp)
    float uh = ((float)h + 0.5f) * SC - 0.5f;
    uh = fminf(fmaxf(uh, 0.0f), (float)(HC-1));
    int h0 = (int)uh; float fh = uh - (float)h0; int h1 = min(h0+1, HC-1);
    float uw = ((float)w + 0.5f) * SC - 0.5f;
    uw = fminf(fmaxf(uw, 0.0f), (float)(WC-1));
    int w0 = (int)uw; float fw = uw - (float)w0; int w1 = min(w0+1, WC-1);

    float c00 = (1.0f - fh) * (1.0f - fw);
    float c01 = (1.0f - fh) * fw;
    float c10 = fh * (1.0f - fw);
    float c11 = fh * fw;

    const float* W00 = &g_cw[(h0*WC + w0)*KK];
    const float* W01 = &g_cw[(h0*WC + w1)*KK];
    const float* W10 = &g_cw[(h1*WC + w0)*KK];
    const float* W11 = &g_cw[(h1*WC + w1)*KK];
    const int*   IDX = &g_cidx[cell*KK];

    float M = -FLT_MAX, ssum = 0.0f;
    float a0 = 0.0f, a1 = 0.0f, a2 = 0.0f, bsacc = 0.0f;
    float Dmin = FLT_MAX;

    for (int k = 0; k < KK; k++) {
        int n = __ldg(&IDX[k]);
        const float4* S4 = &g_seg[n*NSEG];
        const float*  SI = &g_sinv[n*NSEG];
        float md = FLT_MAX;
#pragma unroll
        for (int s = 0; s < NSEG; s++) {
            float4 sg = __ldg(&S4[s]);
            float inv = __ldg(&SI[s]);
            float pax = px - sg.x, pay = py - sg.y;
            float t = (sg.z*pax + sg.w*pay) * inv;
            t = fminf(fmaxf(t, 0.0f), 1.0f);
            float cx = sg.x + t*sg.z;
            float cy = sg.y + t*sg.w;
            float dx = px - cx, dy = py - cy;
            md = fminf(md, dx*dx + dy*dy);
        }
        Dmin = fminf(Dmin, md);
        float L = 100000.0f / (1e-8f + md);   // exact div: softmax-sensitive

        float wk = c00 * __ldg(&W00[k]) + c01 * __ldg(&W01[k])
                 + c10 * __ldg(&W10[k]) + c11 * __ldg(&W11[k]);

        float4 col = __ldg(&g_col4[n]);

        float nM = fmaxf(M, L);
        float rr = __expf(M - nM);            // 1.0 when M unchanged
        float e  = __expf(L - nM);
        ssum  = ssum  * rr + e;
        a0    = a0    * rr + e * col.x;
        a1    = a1    * rr + e * col.y;
        a2    = a2    * rr + e * col.z;
        bsacc = bsacc * rr + e * wk;
        M = nM;
    }

    float inv = 1.0f / ssum;
    float bs  = bsacc * inv;
    float x   = bs - Dmin;
    float mask = 1.0f / (1.0f + expf(-x));
    float omm  = 1.0f - mask;

    int base = (h*WW + w) * 3;
    out[base + 0] = a0 * inv * mask + omm * 0.5f;
    out[base + 1] = a1 * inv * mask + omm * 0.5f;
    out[base + 2] = a2 * inv * mask + omm * 0.5f;
}

// ---------------------------------------------------------------------------
// Launch. Inputs (metadata order): curve_s, curve_e, curve_c, color, location, width
// ---------------------------------------------------------------------------
extern "C" void kernel_launch(void* const* d_in, const int* in_sizes, int n_in,
                              void* d_out, int out_size)
{
    const float* curve_s  = (const float*)d_in[0];
    const float* curve_e  = (const float*)d_in[1];
    const float* curve_c  = (const float*)d_in[2];
    const float* color    = (const float*)d_in[3];
    const float* location = (const float*)d_in[4];
    const float* width    = (const float*)d_in[5];
    float* out = (float*)d_out;

    // block 0: spatial binning; blocks 1..5: bezier/segment/color precompute
    build_kernel<<<1 + (NS + 1023)/1024, 1024>>>(curve_s, curve_e, curve_c,
                                                 location, color);

    dim3 tgrd((WC + 15)/16, (HC + 15)/16);
    topk_kernel<<<tgrd, 256>>>(width);

    dim3 blk(8, 32);
    dim3 grd(WW/8, HH/32);
    render_kernel<<<grd, blk>>>(out);
}